// round 11
// baseline (speedup 1.0000x reference)
#include <cuda_runtime.h>
#include <cuda_bf16.h>
#include <cstdint>

#define W_TOT 8192
#define BATCH 4
#define CH 256
#define HEADS 4
#define HD 64
#define KATT 7
#define PADR 3
#define MROWS 768

// ---------------- scratch ----------------
__device__ float         g_qkv[3ULL * BATCH * CH * W_TOT];          // fp32 q,k,v planes
__device__ __nv_bfloat16 g_xt_hi[(size_t)BATCH * W_TOT * CH];       // x^T hi [b][w][c]
__device__ __nv_bfloat16 g_xt_lo[(size_t)BATCH * W_TOT * CH];       // x^T lo
__device__ __nv_bfloat16 g_a_hi[MROWS * CH];                        // stacked w1,w2,w3 hi
__device__ __nv_bfloat16 g_a_lo[MROWS * CH];

// ---------------- helpers ----------------
__device__ __forceinline__ uint32_t smem_to_u32(const void* p) {
    uint32_t a;
    asm("{ .reg .u64 t; cvta.to.shared.u64 t, %1; cvt.u32.u64 %0, t; }" : "=r"(a) : "l"(p));
    return a;
}
__device__ __forceinline__ void cp_async16(uint32_t saddr, const void* g) {
    asm volatile("cp.async.cg.shared.global [%0], [%1], 16;" :: "r"(saddr), "l"(g));
}
#define CP_COMMIT() asm volatile("cp.async.commit_group;" ::: "memory")
#define CP_WAIT(n)  asm volatile("cp.async.wait_group %0;" :: "n"(n) : "memory")

__device__ __forceinline__ void ldsm4(uint32_t* r, uint32_t addr) {
    asm volatile("ldmatrix.sync.aligned.m8n8.x4.shared.b16 {%0,%1,%2,%3}, [%4];"
                 : "=r"(r[0]), "=r"(r[1]), "=r"(r[2]), "=r"(r[3]) : "r"(addr));
}
__device__ __forceinline__ void mma16816(float* d, const uint32_t* a, const uint32_t* b) {
    asm volatile(
        "mma.sync.aligned.m16n8k16.row.col.f32.bf16.bf16.f32 "
        "{%0,%1,%2,%3}, {%4,%5,%6,%7}, {%8,%9}, {%0,%1,%2,%3};"
        : "+f"(d[0]), "+f"(d[1]), "+f"(d[2]), "+f"(d[3])
        : "r"(a[0]), "r"(a[1]), "r"(a[2]), "r"(a[3]), "r"(b[0]), "r"(b[1]));
}

// ---------------- prep: transpose + hi/lo split of x ----------------
__global__ void transpose_split(const float* __restrict__ x) {
    __shared__ float tile[32][33];
    const int b = blockIdx.z, c0 = blockIdx.y * 32, w0 = blockIdx.x * 32;
    const int tx = threadIdx.x, ty = threadIdx.y;
    const float* xp = x + ((size_t)b * CH + c0) * W_TOT + w0;
#pragma unroll
    for (int i = 0; i < 4; i++)
        tile[ty + i * 8][tx] = xp[(size_t)(ty + i * 8) * W_TOT + tx];
    __syncthreads();
    const size_t ob = ((size_t)b * W_TOT + w0) * CH + c0;
#pragma unroll
    for (int i = 0; i < 4; i++) {
        int r = ty + i * 8;
        float v = tile[tx][r];
        __nv_bfloat16 hi = __float2bfloat16(v);
        float lo = v - __bfloat162float(hi);
        g_xt_hi[ob + (size_t)r * CH + tx] = hi;
        g_xt_lo[ob + (size_t)r * CH + tx] = __float2bfloat16(lo);
    }
}

// ---------------- prep: split weights ----------------
__global__ void convert_w(const float* __restrict__ w1, const float* __restrict__ w2,
                          const float* __restrict__ w3) {
    const int m = blockIdx.x, k = threadIdx.x;
    const float* src = (m < 256) ? w1 : (m < 512) ? w2 : w3;
    float v = src[(size_t)(m & 255) * CH + k];
    __nv_bfloat16 hi = __float2bfloat16(v);
    float lo = v - __bfloat162float(hi);
    g_a_hi[(size_t)m * CH + k] = hi;
    g_a_lo[(size_t)m * CH + k] = __float2bfloat16(lo);
}

// ---------------- HMMA GEMM (R10: fused K=32 chunks, 3-stage, 2 CTAs/SM) ----------------
#define STAGE_B 32768
#define GEMM_SMEM (3 * STAGE_B)
#define NCHUNK 8

__device__ __forceinline__ void stage_chunk(uint32_t sbuf,
                                            const __nv_bfloat16* __restrict__ Ah,
                                            const __nv_bfloat16* __restrict__ Al,
                                            const __nv_bfloat16* __restrict__ Bh,
                                            const __nv_bfloat16* __restrict__ Bl,
                                            int k0, int tid) {
#pragma unroll
    for (int i = tid; i < 512; i += 256) {
        int r = i >> 2, c = i & 3;
        uint32_t off = (uint32_t)(r * 64) + (uint32_t)((c * 16) ^ ((r & 6) << 3));
        size_t go = (size_t)r * CH + k0 + c * 8;
        cp_async16(sbuf + off,         Ah + go);
        cp_async16(sbuf + 8192 + off,  Al + go);
        cp_async16(sbuf + 16384 + off, Bh + go);
        cp_async16(sbuf + 24576 + off, Bl + go);
    }
}

__global__ __launch_bounds__(256, 2) void gemm_mma(const float* __restrict__ b1,
                                                   const float* __restrict__ b2,
                                                   const float* __restrict__ b3) {
    extern __shared__ char smem[];
    const uint32_t sb = smem_to_u32(smem);
    const int tid = threadIdx.x, wid = tid >> 5, lane = tid & 31;
    const int n0 = blockIdx.x * 128, m0 = blockIdx.y * 128, bb = blockIdx.z;
    const int mw = (wid & 1) * 64;
    const int nw = (wid >> 1) * 32;

    const __nv_bfloat16* Ahp = g_a_hi + (size_t)m0 * CH;
    const __nv_bfloat16* Alp = g_a_lo + (size_t)m0 * CH;
    const __nv_bfloat16* Bhp = g_xt_hi + ((size_t)bb * W_TOT + n0) * CH;
    const __nv_bfloat16* Blp = g_xt_lo + ((size_t)bb * W_TOT + n0) * CH;

    float acc[4][4][4];
#pragma unroll
    for (int i = 0; i < 4; i++)
#pragma unroll
        for (int j = 0; j < 4; j++)
#pragma unroll
            for (int e = 0; e < 4; e++) acc[i][j][e] = 0.f;

    const int l15 = lane & 15;
    const uint32_t aSeg = (uint32_t)((lane >> 4) << 4);
    const uint32_t bSeg = (uint32_t)(((lane >> 3) & 1) << 4);
    uint32_t aBase[4], aSw[4], bBase[2], bSw[2];
#pragma unroll
    for (int mi = 0; mi < 4; mi++) {
        int r = mw + mi * 16 + l15;
        aBase[mi] = (uint32_t)(r * 64);
        aSw[mi] = (uint32_t)((r & 6) << 3);
    }
#pragma unroll
    for (int jj = 0; jj < 2; jj++) {
        int r = nw + jj * 16 + (lane & 7) + ((lane >> 4) << 3);
        bBase[jj] = (uint32_t)(r * 64);
        bSw[jj] = (uint32_t)((r & 6) << 3);
    }

    stage_chunk(sb, Ahp, Alp, Bhp, Blp, 0, tid);
    CP_COMMIT();
    stage_chunk(sb + STAGE_B, Ahp, Alp, Bhp, Blp, 32, tid);
    CP_COMMIT();

#pragma unroll
    for (int ck = 0; ck < NCHUNK; ck++) {
        if (ck < NCHUNK - 2) {
            stage_chunk(sb + (uint32_t)(((ck + 2) % 3) * STAGE_B),
                        Ahp, Alp, Bhp, Blp, (ck + 2) * 32, tid);
            CP_COMMIT();
            CP_WAIT(2);
        } else if (ck == NCHUNK - 2) {
            CP_WAIT(1);
        } else {
            CP_WAIT(0);
        }
        __syncthreads();

        const uint32_t sAh = sb + (uint32_t)((ck % 3) * STAGE_B);
        const uint32_t sAl = sAh + 8192;
        const uint32_t sBh = sAh + 16384;
        const uint32_t sBl = sAh + 24576;
#pragma unroll
        for (int kk = 0; kk < 2; kk++) {
            const uint32_t ka = (uint32_t)(kk * 32);
            uint32_t ah[4][4], al[4][4], bh[2][4], bl[2][4];
#pragma unroll
            for (int mi = 0; mi < 4; mi++)
                ldsm4(ah[mi], sAh + aBase[mi] + ((ka + aSeg) ^ aSw[mi]));
#pragma unroll
            for (int jj = 0; jj < 2; jj++)
                ldsm4(bh[jj], sBh + bBase[jj] + ((ka + bSeg) ^ bSw[jj]));
#pragma unroll
            for (int mi = 0; mi < 4; mi++) {
#pragma unroll
                for (int jj = 0; jj < 2; jj++) {
                    mma16816(acc[mi][2 * jj],     ah[mi], &bh[jj][0]);
                    mma16816(acc[mi][2 * jj + 1], ah[mi], &bh[jj][2]);
                }
            }
#pragma unroll
            for (int jj = 0; jj < 2; jj++)
                ldsm4(bl[jj], sBl + bBase[jj] + ((ka + bSeg) ^ bSw[jj]));
#pragma unroll
            for (int mi = 0; mi < 4; mi++) {
#pragma unroll
                for (int jj = 0; jj < 2; jj++) {
                    mma16816(acc[mi][2 * jj],     ah[mi], &bl[jj][0]);
                    mma16816(acc[mi][2 * jj + 1], ah[mi], &bl[jj][2]);
                }
            }
#pragma unroll
            for (int mi = 0; mi < 4; mi++)
                ldsm4(al[mi], sAl + aBase[mi] + ((ka + aSeg) ^ aSw[mi]));
#pragma unroll
            for (int mi = 0; mi < 4; mi++) {
#pragma unroll
                for (int jj = 0; jj < 2; jj++) {
                    mma16816(acc[mi][2 * jj],     al[mi], &bh[jj][0]);
                    mma16816(acc[mi][2 * jj + 1], al[mi], &bh[jj][2]);
                }
            }
        }
        __syncthreads();
    }

    const int t_sel = m0 >> 8;
    const float* bp = (t_sel == 0) ? b1 : (t_sel == 1) ? b2 : b3;
#pragma unroll
    for (int mi = 0; mi < 4; mi++) {
        const int mloc = m0 + mw + mi * 16 + (lane >> 2);
        const int c0r = mloc & 255;
        const float bv0 = __ldg(&bp[c0r]);
        const float bv1 = __ldg(&bp[c0r + 8]);
        float* op0 = g_qkv + (((size_t)t_sel * BATCH + bb) * CH + c0r) * W_TOT + n0;
        float* op1 = op0 + (size_t)8 * W_TOT;
#pragma unroll
        for (int nj = 0; nj < 4; nj++) {
            const int w = nw + nj * 8 + (lane & 3) * 2;
            *(float2*)(op0 + w) = make_float2(acc[mi][nj][0] + bv0, acc[mi][nj][1] + bv0);
            *(float2*)(op1 + w) = make_float2(acc[mi][nj][2] + bv1, acc[mi][nj][3] + bv1);
        }
    }
}

// ---------------- attention + conv epilogue (vectorized: 4 w per thread) ----------------
// Block = 256 threads = 4 dq-groups x 64 threads; each thread owns 4 consecutive w.
// 7-tap windows over 4 w come from 3 aligned float4 loads.
__device__ __forceinline__ int reflect_idx(int pos) {
    return pos < 0 ? -pos : (pos >= W_TOT ? 2 * W_TOT - 2 - pos : pos);
}

__global__ __launch_bounds__(256) void attn_epilogue(
    const float* __restrict__ wp, const float* __restrict__ fc_w,
    const float* __restrict__ dep_w, const float* __restrict__ dep_b,
    const float* __restrict__ r1p, const float* __restrict__ r2p,
    float* __restrict__ out) {
    __shared__ float slog[4][64 * 33];   // [dq][wl*33 + j], j: 0..27 logits, 28..31 qwp

    const int b = blockIdx.z, h = blockIdx.y;
    const int wl = threadIdx.x & 63;
    const int dq = threadIdx.x >> 6;
    const int d0 = dq * 16;
    const int w0 = blockIdx.x * 256 + wl * 4;
    const bool interior = (w0 >= 4) && (w0 + 8 <= W_TOT);

    const float* qb = g_qkv + ((size_t)0 * BATCH + b) * CH * W_TOT;
    const float* kb = g_qkv + ((size_t)1 * BATCH + b) * CH * W_TOT;
    const float* vb = g_qkv + ((size_t)2 * BATCH + b) * CH * W_TOT;
    const float* qg = qb + (size_t)h * HD * W_TOT;
    const float* kg = kb + (size_t)h * HD * W_TOT;
    const float* vg = vb + (size_t)h * HD * W_TOT;

    // ---- phase 1: partial logits over this thread's 16 d's, 4 w's ----
    {
        float part[28];
        float qwp[4] = {0.f, 0.f, 0.f, 0.f};
#pragma unroll
        for (int j = 0; j < 28; j++) part[j] = 0.f;

        if (interior) {
#pragma unroll 4
            for (int i = 0; i < 16; i++) {
                const int d = d0 + i;
                const size_t rowo = (size_t)d * W_TOT;
                const float4 q4 = *(const float4*)(qg + rowo + w0);
                const float wpd = __ldg(&wp[d]);
                float qv[4] = {q4.x * 0.125f, q4.y * 0.125f, q4.z * 0.125f, q4.w * 0.125f};
                const float4 ka = *(const float4*)(kg + rowo + w0 - 4);
                const float4 kc = *(const float4*)(kg + rowo + w0);
                const float4 ke = *(const float4*)(kg + rowo + w0 + 4);
                const float win[12] = {ka.x, ka.y, ka.z, ka.w, kc.x, kc.y, kc.z, kc.w,
                                       ke.x, ke.y, ke.z, ke.w};
#pragma unroll
                for (int wi = 0; wi < 4; wi++) {
                    qwp[wi] += qv[wi] * wpd;
#pragma unroll
                    for (int k = 0; k < KATT; k++)
                        part[wi * 7 + k] += qv[wi] * win[wi + k + 1];
                }
            }
        } else {
#pragma unroll 4
            for (int i = 0; i < 16; i++) {
                const int d = d0 + i;
                const size_t rowo = (size_t)d * W_TOT;
                const float wpd = __ldg(&wp[d]);
#pragma unroll
                for (int wi = 0; wi < 4; wi++) {
                    const int w = w0 + wi;
                    float qd = __ldg(&qg[rowo + w]) * 0.125f;
                    qwp[wi] += qd * wpd;
#pragma unroll
                    for (int k = 0; k < KATT; k++)
                        part[wi * 7 + k] += qd * __ldg(&kg[rowo + reflect_idx(w + k - PADR)]);
                }
            }
        }
        float* sp = &slog[dq][wl * 33];
#pragma unroll
        for (int j = 0; j < 28; j++) sp[j] = part[j];
#pragma unroll
        for (int wi = 0; wi < 4; wi++) sp[28 + wi] = qwp[wi];
    }
    __syncthreads();

    // ---- phase 2: reduce across dq + softmax (redundant per dq) ----
    float att[28];
    {
        const float inv = 2.0f / (float)(W_TOT - 1);
        const float* s0 = &slog[0][wl * 33];
        const float* s1 = &slog[1][wl * 33];
        const float* s2 = &slog[2][wl * 33];
        const float* s3 = &slog[3][wl * 33];
#pragma unroll
        for (int wi = 0; wi < 4; wi++) {
            const int w = w0 + wi;
            float logit[KATT];
#pragma unroll
            for (int k = 0; k < KATT; k++) {
                const int j = wi * 7 + k;
                logit[k] = s0[j] + s1[j] + s2[j] + s3[j];
            }
            const float qw = s0[28 + wi] + s1[28 + wi] + s2[28 + wi] + s3[28 + wi];
#pragma unroll
            for (int k = 0; k < KATT; k++)
                logit[k] += qw * inv * (float)(w - reflect_idx(w + k - PADR));
            float m = logit[0];
#pragma unroll
            for (int k = 1; k < KATT; k++) m = fmaxf(m, logit[k]);
            float ssum = 0.f;
#pragma unroll
            for (int k = 0; k < KATT; k++) {
                att[wi * 7 + k] = __expf(logit[k] - m);
                ssum += att[wi * 7 + k];
            }
            const float rcs = 1.0f / ssum;
#pragma unroll
            for (int k = 0; k < KATT; k++) att[wi * 7 + k] *= rcs;
        }
    }

    // ---- phase 3: conv branch f (4 dd values x 4 w, float4) ----
    float4 fv[4];
    {
        float fcs[12];
#pragma unroll
        for (int i = 0; i < 12; i++) fcs[i] = __ldg(&fc_w[i]);
#pragma unroll
        for (int j = 0; j < 4; j++) {
            const int dd = h * 16 + dq * 4 + j;
            float4 a = make_float4(0.f, 0.f, 0.f, 0.f);
#pragma unroll
            for (int hh = 0; hh < HEADS; hh++) {
                const size_t co = (size_t)(hh * HD + dd) * W_TOT + w0;
                const float4 q4 = *(const float4*)(qb + co);
                const float4 k4 = *(const float4*)(kb + co);
                const float4 v4 = *(const float4*)(vb + co);
                const float cq = fcs[hh], ck = fcs[4 + hh], cv = fcs[8 + hh];
                a.x += cq * q4.x + ck * k4.x + cv * v4.x;
                a.y += cq * q4.y + ck * k4.y + cv * v4.y;
                a.z += cq * q4.z + ck * k4.z + cv * v4.z;
                a.w += cq * q4.w + ck * k4.w + cv * v4.w;
            }
            fv[j] = a;
        }
    }

    // ---- phase 4: output for 16 d's x 4 w ----
    const float r1 = r1p[0], r2 = r2p[0];
    float* outp = out + ((size_t)b * CH + h * HD + d0) * W_TOT + w0;
#pragma unroll 4
    for (int i = 0; i < 16; i++) {
        const size_t rowo = (size_t)i * W_TOT;
        const int d = d0 + i;
        float oa[4];
        if (interior) {
            const float4 va = *(const float4*)(vg + (size_t)d * W_TOT + w0 - 4);
            const float4 vc = *(const float4*)(vg + (size_t)d * W_TOT + w0);
            const float4 ve = *(const float4*)(vg + (size_t)d * W_TOT + w0 + 4);
            const float win[12] = {va.x, va.y, va.z, va.w, vc.x, vc.y, vc.z, vc.w,
                                   ve.x, ve.y, ve.z, ve.w};
#pragma unroll
            for (int wi = 0; wi < 4; wi++) {
                float s = 0.f;
#pragma unroll
                for (int k = 0; k < KATT; k++) s += att[wi * 7 + k] * win[wi + k + 1];
                oa[wi] = s;
            }
        } else {
#pragma unroll
            for (int wi = 0; wi < 4; wi++) {
                const int w = w0 + wi;
                float s = 0.f;
#pragma unroll
                for (int k = 0; k < KATT; k++)
                    s += att[wi * 7 + k] * __ldg(&vg[(size_t)d * W_TOT + reflect_idx(w + k - PADR)]);
                oa[wi] = s;
            }
        }
        const float dw = __ldg(&dep_w[h * HD + d]);
        const float db = __ldg(&dep_b[h * HD + d]);
        const float* fj = (const float*)&fv[i >> 2];
        float4 o;
        o.x = r1 * oa[0] + r2 * (dw * fj[0] + db);
        o.y = r1 * oa[1] + r2 * (dw * fj[1] + db);
        o.z = r1 * oa[2] + r2 * (dw * fj[2] + db);
        o.w = r1 * oa[3] + r2 * (dw * fj[3] + db);
        *(float4*)(outp + rowo) = o;
    }
}

// ---------------- launch ----------------
extern "C" void kernel_launch(void* const* d_in, const int* in_sizes, int n_in,
                              void* d_out, int out_size) {
    const float* x     = (const float*)d_in[0];
    const float* w1    = (const float*)d_in[1];
    const float* b1    = (const float*)d_in[2];
    const float* w2    = (const float*)d_in[3];
    const float* b2    = (const float*)d_in[4];
    const float* w3    = (const float*)d_in[5];
    const float* b3    = (const float*)d_in[6];
    const float* wp    = (const float*)d_in[7];
    // d_in[8] = bp : cancels analytically
    const float* fc_w  = (const float*)d_in[9];
    const float* dep_w = (const float*)d_in[10];
    const float* dep_b = (const float*)d_in[11];
    const float* rate1 = (const float*)d_in[12];
    const float* rate2 = (const float*)d_in[13];
    float* out = (float*)d_out;

    cudaFuncSetAttribute(gemm_mma, cudaFuncAttributeMaxDynamicSharedMemorySize, GEMM_SMEM);

    transpose_split<<<dim3(W_TOT / 32, CH / 32, BATCH), dim3(32, 8)>>>(x);
    convert_w<<<MROWS, 256>>>(w1, w2, w3);
    gemm_mma<<<dim3(W_TOT / 128, MROWS / 128, BATCH), 256, GEMM_SMEM>>>(b1, b2, b3);
    attn_epilogue<<<dim3(W_TOT / 256, HEADS, BATCH), 256>>>(
        wp, fc_w, dep_w, dep_b, rate1, rate2, out);
}

// round 12
// speedup vs baseline: 1.3514x; 1.3514x over previous
#include <cuda_runtime.h>
#include <cuda_fp16.h>
#include <cstdint>

#define W_TOT 8192
#define BATCH 4
#define CH 256
#define HEADS 4
#define HD 64
#define KATT 7
#define PADR 3
#define MROWS 768

// ---------------- scratch ----------------
__device__ float  g_qkv[3ULL * BATCH * CH * W_TOT];          // fp32 q,k,v planes
__device__ __half g_xt_hi[(size_t)BATCH * W_TOT * CH];       // x^T hi [b][w][c]
__device__ __half g_xt_lo[(size_t)BATCH * W_TOT * CH];       // x^T lo
__device__ __half g_a[MROWS * CH];                           // stacked w1,w2,w3 (fp16)

// ---------------- helpers ----------------
__device__ __forceinline__ uint32_t smem_to_u32(const void* p) {
    uint32_t a;
    asm("{ .reg .u64 t; cvta.to.shared.u64 t, %1; cvt.u32.u64 %0, t; }" : "=r"(a) : "l"(p));
    return a;
}
__device__ __forceinline__ void cp_async16(uint32_t saddr, const void* g) {
    asm volatile("cp.async.cg.shared.global [%0], [%1], 16;" :: "r"(saddr), "l"(g));
}
#define CP_COMMIT() asm volatile("cp.async.commit_group;" ::: "memory")
#define CP_WAIT(n)  asm volatile("cp.async.wait_group %0;" :: "n"(n) : "memory")

__device__ __forceinline__ void ldsm4(uint32_t* r, uint32_t addr) {
    asm volatile("ldmatrix.sync.aligned.m8n8.x4.shared.b16 {%0,%1,%2,%3}, [%4];"
                 : "=r"(r[0]), "=r"(r[1]), "=r"(r[2]), "=r"(r[3]) : "r"(addr));
}
__device__ __forceinline__ void mma16816(float* d, const uint32_t* a, const uint32_t* b) {
    asm volatile(
        "mma.sync.aligned.m16n8k16.row.col.f32.f16.f16.f32 "
        "{%0,%1,%2,%3}, {%4,%5,%6,%7}, {%8,%9}, {%0,%1,%2,%3};"
        : "+f"(d[0]), "+f"(d[1]), "+f"(d[2]), "+f"(d[3])
        : "r"(a[0]), "r"(a[1]), "r"(a[2]), "r"(a[3]), "r"(b[0]), "r"(b[1]));
}

// ---------------- prep: transpose + fp16 hi/lo split of x ----------------
__global__ void transpose_split(const float* __restrict__ x) {
    __shared__ float tile[32][33];
    const int b = blockIdx.z, c0 = blockIdx.y * 32, w0 = blockIdx.x * 32;
    const int tx = threadIdx.x, ty = threadIdx.y;
    const float* xp = x + ((size_t)b * CH + c0) * W_TOT + w0;
#pragma unroll
    for (int i = 0; i < 4; i++)
        tile[ty + i * 8][tx] = xp[(size_t)(ty + i * 8) * W_TOT + tx];
    __syncthreads();
    const size_t ob = ((size_t)b * W_TOT + w0) * CH + c0;
#pragma unroll
    for (int i = 0; i < 4; i++) {
        int r = ty + i * 8;
        float v = tile[tx][r];
        __half hi = __float2half_rn(v);
        float lo = v - __half2float(hi);
        g_xt_hi[ob + (size_t)r * CH + tx] = hi;
        g_xt_lo[ob + (size_t)r * CH + tx] = __float2half_rn(lo);
    }
}

// ---------------- prep: convert weights to fp16 ----------------
__global__ void convert_w(const float* __restrict__ w1, const float* __restrict__ w2,
                          const float* __restrict__ w3) {
    const int m = blockIdx.x, k = threadIdx.x;
    const float* src = (m < 256) ? w1 : (m < 512) ? w2 : w3;
    float v = src[(size_t)(m & 255) * CH + k];
    g_a[(size_t)m * CH + k] = __float2half_rn(v);
}

// ---------------- HMMA GEMM: fp16 2-pass (A*Bh + A*Bl), K=32 chunks, 3-stage ----------------
// Per chunk stage A, Bh, Bl (each 128 rows x 64B = 8KB) => 24KB/chunk.
// 64B-row swizzle: off = r*64 + ((c*16) ^ ((r&6)<<3)).
#define STAGE_B 24576
#define GEMM_SMEM (3 * STAGE_B)
#define NCHUNK 8

__device__ __forceinline__ void stage_chunk(uint32_t sbuf,
                                            const __half* __restrict__ Ap,
                                            const __half* __restrict__ Bh,
                                            const __half* __restrict__ Bl,
                                            int k0, int tid) {
#pragma unroll
    for (int i = tid; i < 512; i += 256) {
        int r = i >> 2, c = i & 3;
        uint32_t off = (uint32_t)(r * 64) + (uint32_t)((c * 16) ^ ((r & 6) << 3));
        size_t go = (size_t)r * CH + k0 + c * 8;
        cp_async16(sbuf + off,         Ap + go);
        cp_async16(sbuf + 8192 + off,  Bh + go);
        cp_async16(sbuf + 16384 + off, Bl + go);
    }
}

__global__ __launch_bounds__(256, 2) void gemm_mma(const float* __restrict__ b1,
                                                   const float* __restrict__ b2,
                                                   const float* __restrict__ b3) {
    extern __shared__ char smem[];
    const uint32_t sb = smem_to_u32(smem);
    const int tid = threadIdx.x, wid = tid >> 5, lane = tid & 31;
    const int n0 = blockIdx.x * 128, m0 = blockIdx.y * 128, bb = blockIdx.z;
    const int mw = (wid & 1) * 64;
    const int nw = (wid >> 1) * 32;

    const __half* Ap  = g_a + (size_t)m0 * CH;
    const __half* Bhp = g_xt_hi + ((size_t)bb * W_TOT + n0) * CH;
    const __half* Blp = g_xt_lo + ((size_t)bb * W_TOT + n0) * CH;

    float acc[4][4][4];
#pragma unroll
    for (int i = 0; i < 4; i++)
#pragma unroll
        for (int j = 0; j < 4; j++)
#pragma unroll
            for (int e = 0; e < 4; e++) acc[i][j][e] = 0.f;

    const int l15 = lane & 15;
    const uint32_t aSeg = (uint32_t)((lane >> 4) << 4);
    const uint32_t bSeg = (uint32_t)(((lane >> 3) & 1) << 4);
    uint32_t aBase[4], aSw[4], bBase[2], bSw[2];
#pragma unroll
    for (int mi = 0; mi < 4; mi++) {
        int r = mw + mi * 16 + l15;
        aBase[mi] = (uint32_t)(r * 64);
        aSw[mi] = (uint32_t)((r & 6) << 3);
    }
#pragma unroll
    for (int jj = 0; jj < 2; jj++) {
        int r = nw + jj * 16 + (lane & 7) + ((lane >> 4) << 3);
        bBase[jj] = (uint32_t)(r * 64);
        bSw[jj] = (uint32_t)((r & 6) << 3);
    }

    stage_chunk(sb, Ap, Bhp, Blp, 0, tid);
    CP_COMMIT();
    stage_chunk(sb + STAGE_B, Ap, Bhp, Blp, 32, tid);
    CP_COMMIT();

#pragma unroll
    for (int ck = 0; ck < NCHUNK; ck++) {
        if (ck < NCHUNK - 2) {
            stage_chunk(sb + (uint32_t)(((ck + 2) % 3) * STAGE_B),
                        Ap, Bhp, Blp, (ck + 2) * 32, tid);
            CP_COMMIT();
            CP_WAIT(2);
        } else if (ck == NCHUNK - 2) {
            CP_WAIT(1);
        } else {
            CP_WAIT(0);
        }
        __syncthreads();

        const uint32_t sA  = sb + (uint32_t)((ck % 3) * STAGE_B);
        const uint32_t sBh = sA + 8192;
        const uint32_t sBl = sA + 16384;
#pragma unroll
        for (int kk = 0; kk < 2; kk++) {
            const uint32_t ka = (uint32_t)(kk * 32);
            uint32_t af[4][4], bh[2][4], bl[2][4];
#pragma unroll
            for (int mi = 0; mi < 4; mi++)
                ldsm4(af[mi], sA + aBase[mi] + ((ka + aSeg) ^ aSw[mi]));
#pragma unroll
            for (int jj = 0; jj < 2; jj++)
                ldsm4(bh[jj], sBh + bBase[jj] + ((ka + bSeg) ^ bSw[jj]));
#pragma unroll
            for (int mi = 0; mi < 4; mi++) {
#pragma unroll
                for (int jj = 0; jj < 2; jj++) {
                    mma16816(acc[mi][2 * jj],     af[mi], &bh[jj][0]);
                    mma16816(acc[mi][2 * jj + 1], af[mi], &bh[jj][2]);
                }
            }
#pragma unroll
            for (int jj = 0; jj < 2; jj++)
                ldsm4(bl[jj], sBl + bBase[jj] + ((ka + bSeg) ^ bSw[jj]));
#pragma unroll
            for (int mi = 0; mi < 4; mi++) {
#pragma unroll
                for (int jj = 0; jj < 2; jj++) {
                    mma16816(acc[mi][2 * jj],     af[mi], &bl[jj][0]);
                    mma16816(acc[mi][2 * jj + 1], af[mi], &bl[jj][2]);
                }
            }
        }
        __syncthreads();
    }

    const int t_sel = m0 >> 8;
    const float* bp = (t_sel == 0) ? b1 : (t_sel == 1) ? b2 : b3;
#pragma unroll
    for (int mi = 0; mi < 4; mi++) {
        const int mloc = m0 + mw + mi * 16 + (lane >> 2);
        const int c0r = mloc & 255;
        const float bv0 = __ldg(&bp[c0r]);
        const float bv1 = __ldg(&bp[c0r + 8]);
        float* op0 = g_qkv + (((size_t)t_sel * BATCH + bb) * CH + c0r) * W_TOT + n0;
        float* op1 = op0 + (size_t)8 * W_TOT;
#pragma unroll
        for (int nj = 0; nj < 4; nj++) {
            const int w = nw + nj * 8 + (lane & 3) * 2;
            *(float2*)(op0 + w) = make_float2(acc[mi][nj][0] + bv0, acc[mi][nj][1] + bv0);
            *(float2*)(op1 + w) = make_float2(acc[mi][nj][2] + bv1, acc[mi][nj][3] + bv1);
        }
    }
}

// ---------------- attention + conv epilogue (R8/R10 version — local optimum) ----------------
// Block = 256 threads = 4 dq-groups x 64 consecutive w.
__global__ __launch_bounds__(256) void attn_epilogue(
    const float* __restrict__ wp, const float* __restrict__ fc_w,
    const float* __restrict__ dep_w, const float* __restrict__ dep_b,
    const float* __restrict__ r1p, const float* __restrict__ r2p,
    float* __restrict__ out) {
    __shared__ float slog[4][64][8];   // [dq][wl][k(0..6) | qwp(7)]

    const int b = blockIdx.z, h = blockIdx.y;
    const int wl = threadIdx.x & 63;
    const int dq = threadIdx.x >> 6;
    const int d0 = dq * 16;
    const int w = blockIdx.x * 64 + wl;

    const float* qb = g_qkv + ((size_t)0 * BATCH + b) * CH * W_TOT;
    const float* kb = g_qkv + ((size_t)1 * BATCH + b) * CH * W_TOT;
    const float* vb = g_qkv + ((size_t)2 * BATCH + b) * CH * W_TOT;
    const float* qg = qb + (size_t)h * HD * W_TOT;
    const float* kg = kb + (size_t)h * HD * W_TOT;
    const float* vg = vb + (size_t)h * HD * W_TOT;

    // reflection indices for the 7-tap window
    int pr[KATT];
#pragma unroll
    for (int k = 0; k < KATT; k++) {
        int pos = w + k - PADR;
        pr[k] = pos < 0 ? -pos : (pos >= W_TOT ? 2 * W_TOT - 2 - pos : pos);
    }

    // phase 1: partial logits over this thread's 16 d's
    {
        float part[KATT] = {0.f, 0.f, 0.f, 0.f, 0.f, 0.f, 0.f};
        float qwp = 0.f;
#pragma unroll
        for (int i = 0; i < 16; i++) {
            const int d = d0 + i;
            const size_t rowo = (size_t)d * W_TOT;
            float qd = __ldg(&qg[rowo + w]) * 0.125f;
            qwp += qd * __ldg(&wp[d]);
            const float* kr = kg + rowo;
#pragma unroll
            for (int k = 0; k < KATT; k++) part[k] += qd * __ldg(&kr[pr[k]]);
        }
#pragma unroll
        for (int k = 0; k < KATT; k++) slog[dq][wl][k] = part[k];
        slog[dq][wl][7] = qwp;
    }
    __syncthreads();

    // phase 2: reduce across dq + softmax (redundant per dq, cheap)
    float att[KATT];
    {
        float logit[KATT], qwp;
#pragma unroll
        for (int k = 0; k < KATT; k++)
            logit[k] = slog[0][wl][k] + slog[1][wl][k] + slog[2][wl][k] + slog[3][wl][k];
        qwp = slog[0][wl][7] + slog[1][wl][7] + slog[2][wl][7] + slog[3][wl][7];

        const float inv = 2.0f / (float)(W_TOT - 1);
#pragma unroll
        for (int k = 0; k < KATT; k++) logit[k] += qwp * inv * (float)(w - pr[k]);

        float m = logit[0];
#pragma unroll
        for (int k = 1; k < KATT; k++) m = fmaxf(m, logit[k]);
        float ssum = 0.f;
#pragma unroll
        for (int k = 0; k < KATT; k++) { att[k] = __expf(logit[k] - m); ssum += att[k]; }
        float rcs = 1.0f / ssum;
#pragma unroll
        for (int k = 0; k < KATT; k++) att[k] *= rcs;
    }

    // phase 3: conv branch f for this thread's 4 dd values (dd = h*16 + dq*4 + j)
    float fcs[12];
#pragma unroll
    for (int i = 0; i < 12; i++) fcs[i] = __ldg(&fc_w[i]);
    float fv[4];
#pragma unroll
    for (int j = 0; j < 4; j++) {
        const int dd = h * 16 + dq * 4 + j;
        float f = 0.f;
#pragma unroll
        for (int hh = 0; hh < HEADS; hh++) {
            const size_t co = (size_t)(hh * HD + dd) * W_TOT + w;
            f += fcs[hh]     * __ldg(&qb[co]);
            f += fcs[4 + hh] * __ldg(&kb[co]);
            f += fcs[8 + hh] * __ldg(&vb[co]);
        }
        fv[j] = f;
    }

    // phase 4: output for this thread's 16 d's
    const float r1 = r1p[0], r2 = r2p[0];
    float* outp = out + ((size_t)b * CH + h * HD) * W_TOT + w;
#pragma unroll
    for (int i = 0; i < 16; i++) {
        const int d = d0 + i;
        const size_t rowo = (size_t)d * W_TOT;
        const float* vr = vg + rowo;
        float oa = 0.f;
#pragma unroll
        for (int k = 0; k < KATT; k++) oa += att[k] * __ldg(&vr[pr[k]]);
        const float dw = __ldg(&dep_w[h * HD + d]);
        const float db = __ldg(&dep_b[h * HD + d]);
        outp[rowo] = r1 * oa + r2 * (dw * fv[i >> 2] + db);
    }
}

// ---------------- launch ----------------
extern "C" void kernel_launch(void* const* d_in, const int* in_sizes, int n_in,
                              void* d_out, int out_size) {
    const float* x     = (const float*)d_in[0];
    const float* w1    = (const float*)d_in[1];
    const float* b1    = (const float*)d_in[2];
    const float* w2    = (const float*)d_in[3];
    const float* b2    = (const float*)d_in[4];
    const float* w3    = (const float*)d_in[5];
    const float* b3    = (const float*)d_in[6];
    const float* wp    = (const float*)d_in[7];
    // d_in[8] = bp : cancels analytically
    const float* fc_w  = (const float*)d_in[9];
    const float* dep_w = (const float*)d_in[10];
    const float* dep_b = (const float*)d_in[11];
    const float* rate1 = (const float*)d_in[12];
    const float* rate2 = (const float*)d_in[13];
    float* out = (float*)d_out;

    cudaFuncSetAttribute(gemm_mma, cudaFuncAttributeMaxDynamicSharedMemorySize, GEMM_SMEM);

    transpose_split<<<dim3(W_TOT / 32, CH / 32, BATCH), dim3(32, 8)>>>(x);
    convert_w<<<MROWS, 256>>>(w1, w2, w3);
    gemm_mma<<<dim3(W_TOT / 128, MROWS / 128, BATCH), 256, GEMM_SMEM>>>(b1, b2, b3);
    attn_epilogue<<<dim3(W_TOT / 64, HEADS, BATCH), 256>>>(
        wp, fc_w, dep_w, dep_b, rate1, rate2, out);
}

// round 13
// speedup vs baseline: 1.6583x; 1.2271x over previous
#include <cuda_runtime.h>
#include <cuda_fp16.h>
#include <cstdint>

#define W_TOT 8192
#define BATCH 4
#define CH 256
#define HEADS 4
#define HD 64
#define KATT 7
#define PADR 3
#define MROWS 768

// ---------------- scratch ----------------
__device__ float  g_qkv[3ULL * BATCH * CH * W_TOT];          // fp32 q,k,v planes
__device__ __half g_xt[(size_t)BATCH * W_TOT * CH];          // x^T fp16 [b][w][c]
__device__ __half g_a[MROWS * CH];                           // stacked w1,w2,w3 (fp16)

// ---------------- helpers ----------------
__device__ __forceinline__ uint32_t smem_to_u32(const void* p) {
    uint32_t a;
    asm("{ .reg .u64 t; cvta.to.shared.u64 t, %1; cvt.u32.u64 %0, t; }" : "=r"(a) : "l"(p));
    return a;
}
__device__ __forceinline__ void cp_async16(uint32_t saddr, const void* g) {
    asm volatile("cp.async.cg.shared.global [%0], [%1], 16;" :: "r"(saddr), "l"(g));
}
#define CP_COMMIT() asm volatile("cp.async.commit_group;" ::: "memory")
#define CP_WAIT(n)  asm volatile("cp.async.wait_group %0;" :: "n"(n) : "memory")

__device__ __forceinline__ void ldsm4(uint32_t* r, uint32_t addr) {
    asm volatile("ldmatrix.sync.aligned.m8n8.x4.shared.b16 {%0,%1,%2,%3}, [%4];"
                 : "=r"(r[0]), "=r"(r[1]), "=r"(r[2]), "=r"(r[3]) : "r"(addr));
}
__device__ __forceinline__ void mma16816(float* d, const uint32_t* a, const uint32_t* b) {
    asm volatile(
        "mma.sync.aligned.m16n8k16.row.col.f32.f16.f16.f32 "
        "{%0,%1,%2,%3}, {%4,%5,%6,%7}, {%8,%9}, {%0,%1,%2,%3};"
        : "+f"(d[0]), "+f"(d[1]), "+f"(d[2]), "+f"(d[3])
        : "r"(a[0]), "r"(a[1]), "r"(a[2]), "r"(a[3]), "r"(b[0]), "r"(b[1]));
}

// ---------------- prep: transpose + fp16 convert of x ----------------
__global__ void transpose_split(const float* __restrict__ x) {
    __shared__ float tile[32][33];
    const int b = blockIdx.z, c0 = blockIdx.y * 32, w0 = blockIdx.x * 32;
    const int tx = threadIdx.x, ty = threadIdx.y;
    const float* xp = x + ((size_t)b * CH + c0) * W_TOT + w0;
#pragma unroll
    for (int i = 0; i < 4; i++)
        tile[ty + i * 8][tx] = xp[(size_t)(ty + i * 8) * W_TOT + tx];
    __syncthreads();
    const size_t ob = ((size_t)b * W_TOT + w0) * CH + c0;
#pragma unroll
    for (int i = 0; i < 4; i++) {
        int r = ty + i * 8;
        g_xt[ob + (size_t)r * CH + tx] = __float2half_rn(tile[tx][r]);
    }
}

// ---------------- prep: convert weights to fp16 ----------------
__global__ void convert_w(const float* __restrict__ w1, const float* __restrict__ w2,
                          const float* __restrict__ w3) {
    const int m = blockIdx.x, k = threadIdx.x;
    const float* src = (m < 256) ? w1 : (m < 512) ? w2 : w3;
    g_a[(size_t)m * CH + k] = __float2half_rn(src[(size_t)(m & 255) * CH + k]);
}

// ---------------- HMMA GEMM: fp16 1-pass, K=64 chunks (R4 addressing), 3-stage ----------------
// Per chunk stage A(16KB) + B(16KB); 128B rows, swizzle (c*16)^((r&7)<<4).
#define STAGE_B 32768
#define GEMM_SMEM (3 * STAGE_B)
#define NCHUNK 4

__device__ __forceinline__ void stage_chunk(uint32_t sbuf,
                                            const __half* __restrict__ Ap,
                                            const __half* __restrict__ Bp,
                                            int k0, int tid) {
#pragma unroll
    for (int i = tid; i < 1024; i += 256) {
        int r = i >> 3, c = i & 7;
        uint32_t off = (uint32_t)(r * 128) + (uint32_t)((c * 16) ^ ((r & 7) << 4));
        size_t go = (size_t)r * CH + k0 + c * 8;
        cp_async16(sbuf + off,         Ap + go);
        cp_async16(sbuf + 16384 + off, Bp + go);
    }
}

__global__ __launch_bounds__(256, 2) void gemm_mma(const float* __restrict__ b1,
                                                   const float* __restrict__ b2,
                                                   const float* __restrict__ b3) {
    extern __shared__ char smem[];
    const uint32_t sb = smem_to_u32(smem);
    const int tid = threadIdx.x, wid = tid >> 5, lane = tid & 31;
    const int n0 = blockIdx.x * 128, m0 = blockIdx.y * 128, bb = blockIdx.z;
    const int mw = (wid & 1) * 64;
    const int nw = (wid >> 1) * 32;

    const __half* Ap = g_a + (size_t)m0 * CH;
    const __half* Bp = g_xt + ((size_t)bb * W_TOT + n0) * CH;

    float acc[4][4][4];
#pragma unroll
    for (int i = 0; i < 4; i++)
#pragma unroll
        for (int j = 0; j < 4; j++)
#pragma unroll
            for (int e = 0; e < 4; e++) acc[i][j][e] = 0.f;

    // R4-validated ldmatrix lane addressing (128B rows)
    const int l15 = lane & 15, lhi = lane >> 4;
    const uint32_t xorv = (uint32_t)((lane & 7) << 4);
    uint32_t aRow[4], bRow[2];
#pragma unroll
    for (int mi = 0; mi < 4; mi++) aRow[mi] = (uint32_t)((mw + mi * 16 + l15) * 128);
#pragma unroll
    for (int jj = 0; jj < 2; jj++)
        bRow[jj] = (uint32_t)((nw + jj * 16 + (lane & 7) + ((lane >> 4) << 3)) * 128);
    const uint32_t aKb[4] = {
        (uint32_t)((0 * 32 + lhi * 16) ^ xorv), (uint32_t)((1 * 32 + lhi * 16) ^ xorv),
        (uint32_t)((2 * 32 + lhi * 16) ^ xorv), (uint32_t)((3 * 32 + lhi * 16) ^ xorv)};
    const uint32_t bKb[4] = {
        (uint32_t)((0 * 32 + (((lane >> 3) & 1) << 4)) ^ xorv),
        (uint32_t)((1 * 32 + (((lane >> 3) & 1) << 4)) ^ xorv),
        (uint32_t)((2 * 32 + (((lane >> 3) & 1) << 4)) ^ xorv),
        (uint32_t)((3 * 32 + (((lane >> 3) & 1) << 4)) ^ xorv)};

    // prologue: stage chunks 0,1
    stage_chunk(sb, Ap, Bp, 0, tid);
    CP_COMMIT();
    stage_chunk(sb + STAGE_B, Ap, Bp, 64, tid);
    CP_COMMIT();

#pragma unroll
    for (int ck = 0; ck < NCHUNK; ck++) {
        if (ck < NCHUNK - 2) {
            stage_chunk(sb + (uint32_t)(((ck + 2) % 3) * STAGE_B), Ap, Bp,
                        (ck + 2) * 64, tid);
            CP_COMMIT();
            CP_WAIT(2);
        } else if (ck == NCHUNK - 2) {
            CP_WAIT(1);
        } else {
            CP_WAIT(0);
        }
        __syncthreads();

        const uint32_t sA = sb + (uint32_t)((ck % 3) * STAGE_B);
        const uint32_t sB = sA + 16384;
#pragma unroll
        for (int kk = 0; kk < 4; kk++) {
            uint32_t af[4][4], bf[2][4];
#pragma unroll
            for (int mi = 0; mi < 4; mi++) ldsm4(af[mi], sA + aRow[mi] + aKb[kk]);
#pragma unroll
            for (int jj = 0; jj < 2; jj++) ldsm4(bf[jj], sB + bRow[jj] + bKb[kk]);
#pragma unroll
            for (int mi = 0; mi < 4; mi++) {
#pragma unroll
                for (int jj = 0; jj < 2; jj++) {
                    mma16816(acc[mi][2 * jj],     af[mi], &bf[jj][0]);
                    mma16816(acc[mi][2 * jj + 1], af[mi], &bf[jj][2]);
                }
            }
        }
        __syncthreads();
    }

    const int t_sel = m0 >> 8;
    const float* bp = (t_sel == 0) ? b1 : (t_sel == 1) ? b2 : b3;
#pragma unroll
    for (int mi = 0; mi < 4; mi++) {
        const int mloc = m0 + mw + mi * 16 + (lane >> 2);
        const int c0r = mloc & 255;
        const float bv0 = __ldg(&bp[c0r]);
        const float bv1 = __ldg(&bp[c0r + 8]);
        float* op0 = g_qkv + (((size_t)t_sel * BATCH + bb) * CH + c0r) * W_TOT + n0;
        float* op1 = op0 + (size_t)8 * W_TOT;
#pragma unroll
        for (int nj = 0; nj < 4; nj++) {
            const int w = nw + nj * 8 + (lane & 3) * 2;
            *(float2*)(op0 + w) = make_float2(acc[mi][nj][0] + bv0, acc[mi][nj][1] + bv0);
            *(float2*)(op1 + w) = make_float2(acc[mi][nj][2] + bv1, acc[mi][nj][3] + bv1);
        }
    }
}

// ---------------- attention + conv epilogue (R8 version — local optimum) ----------------
// Block = 256 threads = 4 dq-groups x 64 consecutive w.
__global__ __launch_bounds__(256) void attn_epilogue(
    const float* __restrict__ wp, const float* __restrict__ fc_w,
    const float* __restrict__ dep_w, const float* __restrict__ dep_b,
    const float* __restrict__ r1p, const float* __restrict__ r2p,
    float* __restrict__ out) {
    __shared__ float slog[4][64][8];   // [dq][wl][k(0..6) | qwp(7)]

    const int b = blockIdx.z, h = blockIdx.y;
    const int wl = threadIdx.x & 63;
    const int dq = threadIdx.x >> 6;
    const int d0 = dq * 16;
    const int w = blockIdx.x * 64 + wl;

    const float* qb = g_qkv + ((size_t)0 * BATCH + b) * CH * W_TOT;
    const float* kb = g_qkv + ((size_t)1 * BATCH + b) * CH * W_TOT;
    const float* vb = g_qkv + ((size_t)2 * BATCH + b) * CH * W_TOT;
    const float* qg = qb + (size_t)h * HD * W_TOT;
    const float* kg = kb + (size_t)h * HD * W_TOT;
    const float* vg = vb + (size_t)h * HD * W_TOT;

    // reflection indices for the 7-tap window
    int pr[KATT];
#pragma unroll
    for (int k = 0; k < KATT; k++) {
        int pos = w + k - PADR;
        pr[k] = pos < 0 ? -pos : (pos >= W_TOT ? 2 * W_TOT - 2 - pos : pos);
    }

    // phase 1: partial logits over this thread's 16 d's
    {
        float part[KATT] = {0.f, 0.f, 0.f, 0.f, 0.f, 0.f, 0.f};
        float qwp = 0.f;
#pragma unroll
        for (int i = 0; i < 16; i++) {
            const int d = d0 + i;
            const size_t rowo = (size_t)d * W_TOT;
            float qd = __ldg(&qg[rowo + w]) * 0.125f;
            qwp += qd * __ldg(&wp[d]);
            const float* kr = kg + rowo;
#pragma unroll
            for (int k = 0; k < KATT; k++) part[k] += qd * __ldg(&kr[pr[k]]);
        }
#pragma unroll
        for (int k = 0; k < KATT; k++) slog[dq][wl][k] = part[k];
        slog[dq][wl][7] = qwp;
    }
    __syncthreads();

    // phase 2: reduce across dq + softmax (redundant per dq, cheap)
    float att[KATT];
    {
        float logit[KATT], qwp;
#pragma unroll
        for (int k = 0; k < KATT; k++)
            logit[k] = slog[0][wl][k] + slog[1][wl][k] + slog[2][wl][k] + slog[3][wl][k];
        qwp = slog[0][wl][7] + slog[1][wl][7] + slog[2][wl][7] + slog[3][wl][7];

        const float inv = 2.0f / (float)(W_TOT - 1);
#pragma unroll
        for (int k = 0; k < KATT; k++) logit[k] += qwp * inv * (float)(w - pr[k]);

        float m = logit[0];
#pragma unroll
        for (int k = 1; k < KATT; k++) m = fmaxf(m, logit[k]);
        float ssum = 0.f;
#pragma unroll
        for (int k = 0; k < KATT; k++) { att[k] = __expf(logit[k] - m); ssum += att[k]; }
        float rcs = 1.0f / ssum;
#pragma unroll
        for (int k = 0; k < KATT; k++) att[k] *= rcs;
    }

    // phase 3: conv branch f for this thread's 4 dd values (dd = h*16 + dq*4 + j)
    float fcs[12];
#pragma unroll
    for (int i = 0; i < 12; i++) fcs[i] = __ldg(&fc_w[i]);
    float fv[4];
#pragma unroll
    for (int j = 0; j < 4; j++) {
        const int dd = h * 16 + dq * 4 + j;
        float f = 0.f;
#pragma unroll
        for (int hh = 0; hh < HEADS; hh++) {
            const size_t co = (size_t)(hh * HD + dd) * W_TOT + w;
            f += fcs[hh]     * __ldg(&qb[co]);
            f += fcs[4 + hh] * __ldg(&kb[co]);
            f += fcs[8 + hh] * __ldg(&vb[co]);
        }
        fv[j] = f;
    }

    // phase 4: output for this thread's 16 d's
    const float r1 = r1p[0], r2 = r2p[0];
    float* outp = out + ((size_t)b * CH + h * HD) * W_TOT + w;
#pragma unroll
    for (int i = 0; i < 16; i++) {
        const int d = d0 + i;
        const size_t rowo = (size_t)d * W_TOT;
        const float* vr = vg + rowo;
        float oa = 0.f;
#pragma unroll
        for (int k = 0; k < KATT; k++) oa += att[k] * __ldg(&vr[pr[k]]);
        const float dw = __ldg(&dep_w[h * HD + d]);
        const float db = __ldg(&dep_b[h * HD + d]);
        outp[rowo] = r1 * oa + r2 * (dw * fv[i >> 2] + db);
    }
}

// ---------------- launch ----------------
extern "C" void kernel_launch(void* const* d_in, const int* in_sizes, int n_in,
                              void* d_out, int out_size) {
    const float* x     = (const float*)d_in[0];
    const float* w1    = (const float*)d_in[1];
    const float* b1    = (const float*)d_in[2];
    const float* w2    = (const float*)d_in[3];
    const float* b2    = (const float*)d_in[4];
    const float* w3    = (const float*)d_in[5];
    const float* b3    = (const float*)d_in[6];
    const float* wp    = (const float*)d_in[7];
    // d_in[8] = bp : cancels analytically
    const float* fc_w  = (const float*)d_in[9];
    const float* dep_w = (const float*)d_in[10];
    const float* dep_b = (const float*)d_in[11];
    const float* rate1 = (const float*)d_in[12];
    const float* rate2 = (const float*)d_in[13];
    float* out = (float*)d_out;

    cudaFuncSetAttribute(gemm_mma, cudaFuncAttributeMaxDynamicSharedMemorySize, GEMM_SMEM);

    transpose_split<<<dim3(W_TOT / 32, CH / 32, BATCH), dim3(32, 8)>>>(x);
    convert_w<<<MROWS, 256>>>(w1, w2, w3);
    gemm_mma<<<dim3(W_TOT / 128, MROWS / 128, BATCH), 256, GEMM_SMEM>>>(b1, b2, b3);
    attn_epilogue<<<dim3(W_TOT / 64, HEADS, BATCH), 256>>>(
        wp, fc_w, dep_w, dep_b, rate1, rate2, out);
}